// round 4
// baseline (speedup 1.0000x reference)
#include <cuda_runtime.h>
#include <cuda_bf16.h>
#include <math.h>
#include <stdint.h>

// Problem constants
#define Bc   8
#define Sc   1024
#define Ec   512
#define Hc   8
#define HDc  64
#define Pc   32
#define Nt   (Bc*Sc)     // 8192 tokens
#define HIDc 2048

// ---------------- scratch (device globals; allocation-free) ----------------
__device__ float g_qkv[Nt*3*Ec];     // in_proj output [8192,1536]
__device__ float g_qkvd[Nt*3*Ec];    // dq|dk|dv packed [8192,1536]
__device__ float g_lo[Nt*Ec];
__device__ float g_local[Nt*Ec];
__device__ float g_h1[Nt*Ec];
__device__ float g_offraw[Nt*Hc*Pc];
__device__ int   g_sp[Nt*Pc];
__device__ float g_lattn[Nt*Ec];
__device__ float g_long[Nt*Ec];
__device__ float g_gh[Nt*Ec];
__device__ float g_gate[Nt*Ec];
__device__ float g_x1[Nt*Ec];
__device__ float g_ffnh[Nt*HIDc];
__device__ float g_f[Nt*Ec];
__device__ int   g_vl[Bc];

// ---------------- TF32 helpers ----------------------------------------------
__device__ __forceinline__ uint32_t f2tf(float f) {
    uint32_t u;
    asm("cvt.rna.tf32.f32 %0, %1;" : "=r"(u) : "f"(f));
    return u;
}

__device__ __forceinline__ void mma_tf32(float4& d, const uint32_t* a, uint32_t b0, uint32_t b1) {
    asm volatile(
        "mma.sync.aligned.m16n8k8.row.col.f32.tf32.tf32.f32 "
        "{%0,%1,%2,%3}, {%4,%5,%6,%7}, {%8,%9}, {%0,%1,%2,%3};"
        : "+f"(d.x), "+f"(d.y), "+f"(d.z), "+f"(d.w)
        : "r"(a[0]), "r"(a[1]), "r"(a[2]), "r"(a[3]),
          "r"(b0), "r"(b1));
}

__device__ __forceinline__ float apply_epi(float v, int EPI) {
    if (EPI == 1)      return 0.5f * v * (1.f + erff(v * 0.70710678118654752f));
    else if (EPI == 2) return tanhf(v);
    else if (EPI == 3) return 1.f / (1.f + expf(-v));
    return v;
}

// A-pointer table: p[kt>>9] gives the source for k in [512*i, 512*(i+1)),
// each with row stride `stride`; column within source = kt & 511.
struct APtrs { const float* p[4]; int stride; };

#define SM_U4   1032              // 8*129 uint4 per buffer
#define SMEM_BYTES (4*SM_U4*16)   // 2 bufs x (A+B)

// ============================================================================
// Double-buffered TF32 GEMM: C[M,N] = A[M,K] @ B[N,K]^T + bias, epilogue EPI.
// CTA 128x128, ktile 32, 8 warps (warp 32m x 64n). M%128==0,N%128==0,K%32==0.
// ============================================================================
template<int EPI>
__global__ __launch_bounds__(256, 2) void tgemm(
    APtrs ap, const float* __restrict__ Bw,
    const float* __restrict__ bias, float* __restrict__ C,
    int M, int N, int K)
{
    extern __shared__ uint4 smem[];
    uint4* sAb[2] = { smem,            smem + SM_U4   };
    uint4* sBb[2] = { smem + 2*SM_U4,  smem + 3*SM_U4 };

    const int t    = threadIdx.x;
    const int lane = t & 31;
    const int w    = t >> 5;
    const int wm   = w & 3;
    const int wn   = w >> 2;
    const long rowBase = (long)blockIdx.y * 128;
    const long colBase = (long)blockIdx.x * 128;

    const int rrow = t >> 3;   // 0..31
    const int kq8  = t & 7;    // 0..7

    float4 acc[2][8];
#pragma unroll
    for (int mt = 0; mt < 2; mt++)
#pragma unroll
        for (int nt = 0; nt < 8; nt++) acc[mt][nt] = make_float4(0.f,0.f,0.f,0.f);

    // ---- prologue: tile 0 -> buf 0 ----
    {
        const float* srcA = ap.p[0];
        int kloc = kq8 * 4;
#pragma unroll
        for (int i = 0; i < 4; i++) {
            float4 av = *reinterpret_cast<const float4*>(srcA + (rowBase + rrow + 32*i) * (long)ap.stride + kloc);
            sAb[0][kq8*129 + rrow + 32*i] = make_uint4(f2tf(av.x), f2tf(av.y), f2tf(av.z), f2tf(av.w));
            float4 bv = *reinterpret_cast<const float4*>(Bw + (colBase + rrow + 32*i) * (long)K + kloc);
            sBb[0][kq8*129 + rrow + 32*i] = make_uint4(f2tf(bv.x), f2tf(bv.y), f2tf(bv.z), f2tf(bv.w));
        }
    }
    __syncthreads();

    const int c = lane & 3;
    const int q = lane >> 2;
    const int nT = K >> 5;
    int cur = 0;

    for (int ti = 0; ti < nT; ti++) {
        const bool nxt = (ti + 1) < nT;
        float4 stA[4], stB[4];
        if (nxt) {
            int kt = (ti + 1) << 5;
            const float* srcA = ap.p[kt >> 9];
            int kloc = (kt & 511) + kq8 * 4;
#pragma unroll
            for (int i = 0; i < 4; i++)
                stA[i] = *reinterpret_cast<const float4*>(srcA + (rowBase + rrow + 32*i) * (long)ap.stride + kloc);
#pragma unroll
            for (int i = 0; i < 4; i++)
                stB[i] = *reinterpret_cast<const float4*>(Bw + (colBase + rrow + 32*i) * (long)K + kt + kq8*4);
        }

        const uint32_t* sAw = reinterpret_cast<const uint32_t*>(sAb[cur]);
        const uint32_t* sBw = reinterpret_cast<const uint32_t*>(sBb[cur]);
#pragma unroll
        for (int s = 0; s < 4; s++) {
            uint32_t af[2][4];
#pragma unroll
            for (int mt = 0; mt < 2; mt++) {
                int m = wm*32 + mt*16 + q;
                af[mt][0] = sAw[((2*s+0)*129 + m    )*4 + c];
                af[mt][1] = sAw[((2*s+0)*129 + m + 8)*4 + c];
                af[mt][2] = sAw[((2*s+1)*129 + m    )*4 + c];
                af[mt][3] = sAw[((2*s+1)*129 + m + 8)*4 + c];
            }
#pragma unroll
            for (int nt = 0; nt < 8; nt++) {
                int n = wn*64 + nt*8 + q;
                uint32_t b0 = sBw[((2*s+0)*129 + n)*4 + c];
                uint32_t b1 = sBw[((2*s+1)*129 + n)*4 + c];
                mma_tf32(acc[0][nt], af[0], b0, b1);
                mma_tf32(acc[1][nt], af[1], b0, b1);
            }
        }

        if (nxt) {
            int nb = cur ^ 1;
#pragma unroll
            for (int i = 0; i < 4; i++) {
                sAb[nb][kq8*129 + rrow + 32*i] = make_uint4(f2tf(stA[i].x), f2tf(stA[i].y), f2tf(stA[i].z), f2tf(stA[i].w));
                sBb[nb][kq8*129 + rrow + 32*i] = make_uint4(f2tf(stB[i].x), f2tf(stB[i].y), f2tf(stB[i].z), f2tf(stB[i].w));
            }
            __syncthreads();
            cur = nb;
        }
    }

    // ---- epilogue ----
    const int c2 = (lane & 3) * 2;
#pragma unroll
    for (int mt = 0; mt < 2; mt++) {
        long r0 = rowBase + wm*32 + mt*16 + q;
        long r1 = r0 + 8;
#pragma unroll
        for (int nt = 0; nt < 8; nt++) {
            int col = (int)colBase + wn*64 + nt*8 + c2;
            float b0 = bias[col], b1 = bias[col+1];
            float4 a = acc[mt][nt];
            *reinterpret_cast<float2*>(C + r0 * N + col) =
                make_float2(apply_epi(a.x + b0, EPI), apply_epi(a.y + b1, EPI));
            *reinterpret_cast<float2*>(C + r1 * N + col) =
                make_float2(apply_epi(a.z + b0, EPI), apply_epi(a.w + b1, EPI));
        }
    }
}

// ============================================================================
// Segmented GEMM (K=512): per-CTA segment selects A, B, bias, C, epi.
// ============================================================================
struct Seg {
    const float* A; const float* B; const float* bias; float* C;
    int N;       // C row stride
    int colOff;  // column offset into C
    int epi;
    int bStart;  // first blockIdx.x of this segment
};
struct SegArgs { Seg s[5]; int nseg; };

__global__ __launch_bounds__(256, 2) void tgemm_seg(SegArgs sa)
{
    extern __shared__ uint4 smem[];
    uint4* sAb[2] = { smem,            smem + SM_U4   };
    uint4* sBb[2] = { smem + 2*SM_U4,  smem + 3*SM_U4 };

    int si = 0;
#pragma unroll
    for (int i = 1; i < 5; i++)
        if (i < sa.nseg && (int)blockIdx.x >= sa.s[i].bStart) si = i;
    const Seg sg = sa.s[si];
    const int localCol = ((int)blockIdx.x - sg.bStart) * 128;

    const int t    = threadIdx.x;
    const int lane = t & 31;
    const int w    = t >> 5;
    const int wm   = w & 3;
    const int wn   = w >> 2;
    const long rowBase = (long)blockIdx.y * 128;
    const int rrow = t >> 3;
    const int kq8  = t & 7;
    const int K = 512;

    float4 acc[2][8];
#pragma unroll
    for (int mt = 0; mt < 2; mt++)
#pragma unroll
        for (int nt = 0; nt < 8; nt++) acc[mt][nt] = make_float4(0.f,0.f,0.f,0.f);

    {
        int kloc = kq8 * 4;
#pragma unroll
        for (int i = 0; i < 4; i++) {
            float4 av = *reinterpret_cast<const float4*>(sg.A + (rowBase + rrow + 32*i) * (long)K + kloc);
            sAb[0][kq8*129 + rrow + 32*i] = make_uint4(f2tf(av.x), f2tf(av.y), f2tf(av.z), f2tf(av.w));
            float4 bv = *reinterpret_cast<const float4*>(sg.B + (localCol + rrow + 32*i) * (long)K + kloc);
            sBb[0][kq8*129 + rrow + 32*i] = make_uint4(f2tf(bv.x), f2tf(bv.y), f2tf(bv.z), f2tf(bv.w));
        }
    }
    __syncthreads();

    const int c = lane & 3;
    const int q = lane >> 2;
    int cur = 0;

    for (int ti = 0; ti < 16; ti++) {
        const bool nxt = ti < 15;
        float4 stA[4], stB[4];
        if (nxt) {
            int kt = (ti + 1) << 5;
#pragma unroll
            for (int i = 0; i < 4; i++)
                stA[i] = *reinterpret_cast<const float4*>(sg.A + (rowBase + rrow + 32*i) * (long)K + kt + kq8*4);
#pragma unroll
            for (int i = 0; i < 4; i++)
                stB[i] = *reinterpret_cast<const float4*>(sg.B + (localCol + rrow + 32*i) * (long)K + kt + kq8*4);
        }

        const uint32_t* sAw = reinterpret_cast<const uint32_t*>(sAb[cur]);
        const uint32_t* sBw = reinterpret_cast<const uint32_t*>(sBb[cur]);
#pragma unroll
        for (int s = 0; s < 4; s++) {
            uint32_t af[2][4];
#pragma unroll
            for (int mt = 0; mt < 2; mt++) {
                int m = wm*32 + mt*16 + q;
                af[mt][0] = sAw[((2*s+0)*129 + m    )*4 + c];
                af[mt][1] = sAw[((2*s+0)*129 + m + 8)*4 + c];
                af[mt][2] = sAw[((2*s+1)*129 + m    )*4 + c];
                af[mt][3] = sAw[((2*s+1)*129 + m + 8)*4 + c];
            }
#pragma unroll
            for (int nt = 0; nt < 8; nt++) {
                int n = wn*64 + nt*8 + q;
                uint32_t b0 = sBw[((2*s+0)*129 + n)*4 + c];
                uint32_t b1 = sBw[((2*s+1)*129 + n)*4 + c];
                mma_tf32(acc[0][nt], af[0], b0, b1);
                mma_tf32(acc[1][nt], af[1], b0, b1);
            }
        }

        if (nxt) {
            int nb = cur ^ 1;
#pragma unroll
            for (int i = 0; i < 4; i++) {
                sAb[nb][kq8*129 + rrow + 32*i] = make_uint4(f2tf(stA[i].x), f2tf(stA[i].y), f2tf(stA[i].z), f2tf(stA[i].w));
                sBb[nb][kq8*129 + rrow + 32*i] = make_uint4(f2tf(stB[i].x), f2tf(stB[i].y), f2tf(stB[i].z), f2tf(stB[i].w));
            }
            __syncthreads();
            cur = nb;
        }
    }

    const int c2 = (lane & 3) * 2;
#pragma unroll
    for (int mt = 0; mt < 2; mt++) {
        long r0 = rowBase + wm*32 + mt*16 + q;
        long r1 = r0 + 8;
#pragma unroll
        for (int nt = 0; nt < 8; nt++) {
            int colL = localCol + wn*64 + nt*8 + c2;
            float b0 = sg.bias[colL], b1 = sg.bias[colL+1];
            float4 a = acc[mt][nt];
            float* C0 = sg.C + r0 * (long)sg.N + sg.colOff + colL;
            float* C1 = sg.C + r1 * (long)sg.N + sg.colOff + colL;
            *reinterpret_cast<float2*>(C0) =
                make_float2(apply_epi(a.x + b0, sg.epi), apply_epi(a.y + b1, sg.epi));
            *reinterpret_cast<float2*>(C1) =
                make_float2(apply_epi(a.z + b0, sg.epi), apply_epi(a.w + b1, sg.epi));
        }
    }
}

// ---------------- local windowed attention: one warp per (token, head) -----
__global__ __launch_bounds__(256) void local_attn_kernel(const int* __restrict__ pad)
{
    int gwarp = (blockIdx.x * blockDim.x + threadIdx.x) >> 5;
    int lane  = threadIdx.x & 31;
    if (gwarp >= Nt * Hc) return;
    int h = gwarp % Hc;
    int n = gwarp / Hc;
    int b = n / Sc, q = n % Sc;

    const float* base = g_qkv + (long)n * (3*Ec);
    float2 qv = *reinterpret_cast<const float2*>(base + h*HDc + lane*2);

    float sc[4]; bool val[4];
#pragma unroll
    for (int w = 0; w < 4; w++) {
        int kpos = q - 3 + w;
        bool v = (kpos >= 0) && (pad[b*Sc + kpos] == 0);
        float s = 0.f;
        if (v) {
            float2 kv = *reinterpret_cast<const float2*>(
                g_qkv + ((long)(b*Sc + kpos)) * (3*Ec) + Ec + h*HDc + lane*2);
            s = qv.x*kv.x + qv.y*kv.y;
        }
#pragma unroll
        for (int o = 16; o > 0; o >>= 1) s += __shfl_xor_sync(0xffffffffu, s, o);
        sc[w]  = s * 0.125f;
        val[w] = v;
    }
    float m = -INFINITY;
#pragma unroll
    for (int w = 0; w < 4; w++) if (val[w]) m = fmaxf(m, sc[w]);
    float e[4]; float den = 0.f;
#pragma unroll
    for (int w = 0; w < 4; w++) { e[w] = val[w] ? expf(sc[w] - m) : 0.f; den += e[w]; }

    float2 o = make_float2(0.f, 0.f);
    if (den > 0.f) {
        float inv = 1.f / den;
#pragma unroll
        for (int w = 0; w < 4; w++) {
            if (!val[w]) continue;
            int kpos = q - 3 + w;
            float a = e[w] * inv;
            float2 vv = *reinterpret_cast<const float2*>(
                g_qkv + ((long)(b*Sc + kpos)) * (3*Ec) + 2*Ec + h*HDc + lane*2);
            o.x += a * vv.x; o.y += a * vv.y;
        }
    }
    *reinterpret_cast<float2*>(g_lo + (long)n*Ec + h*HDc + lane*2) = o;
}

// ---------------- valid length per batch ------------------------------------
__global__ void valid_len_kernel(const int* __restrict__ pad)
{
    int b = blockIdx.x;
    __shared__ int cnt;
    if (threadIdx.x == 0) cnt = 0;
    __syncthreads();
    int c = 0;
    for (int s = threadIdx.x; s < Sc; s += blockDim.x) c += (pad[b*Sc + s] != 0);
    atomicAdd(&cnt, c);
    __syncthreads();
    if (threadIdx.x == 0) {
        int v = Sc - cnt;
        g_vl[b] = v < 1 ? 1 : v;
    }
}

// ---------------- sampled positions: 32 lanes per token ---------------------
__global__ void sample_kernel()
{
    int idx = blockIdx.x * blockDim.x + threadIdx.x;
    int n = idx >> 5, p = idx & 31;
    if (n >= Nt) return;
    int b = n / Sc, s = n % Sc;

    float off = 0.f;
#pragma unroll
    for (int h = 0; h < Hc; h++) off += g_offraw[(long)n*(Hc*Pc) + h*Pc + p];

    float pos    = (float)s;
    float delta  = (0.9f - 0.1f) / 31.0f;
    float anchor = (p == 31) ? 0.9f : fmaf((float)p, delta, 0.1f);
    float samp   = anchor * pos + off;
    float lob    = fmaxf(pos - 256.f, 0.f);
    samp = fminf(fmaxf(samp, lob), pos);
    samp = fminf(samp, (float)(g_vl[b] - 1));
    g_sp[(long)n*Pc + p] = (int)rintf(samp);
}

// ---------------- long deformable attention: one block per token ------------
__global__ __launch_bounds__(256) void long_attn_kernel(const int* __restrict__ pad)
{
    int n = blockIdx.x;
    int b = n / Sc, q = n % Sc;
    int tid = threadIdx.x, lane = tid & 31, warp = tid >> 5;

    __shared__ float s_sc[Pc];
    __shared__ float s_a[Pc];
    __shared__ int   s_j[Pc];
    if (tid < Pc) s_j[tid] = g_sp[(long)n*Pc + tid];
    __syncthreads();

    const float* qrow = g_qkvd + (long)n * 1536;                 // dq block
#pragma unroll
    for (int i = 0; i < 4; i++) {
        int p = warp*4 + i;
        int j = s_j[p];
        const float* krow = g_qkvd + ((long)b*Sc + j) * 1536 + 512;  // dk block
        float s = 0.f;
#pragma unroll
        for (int t = 0; t < 4; t++) {
            float4 a = *reinterpret_cast<const float4*>(qrow + t*128 + lane*4);
            float4 k = *reinterpret_cast<const float4*>(krow + t*128 + lane*4);
            s += a.x*k.x + a.y*k.y + a.z*k.z + a.w*k.w;
        }
#pragma unroll
        for (int o = 16; o > 0; o >>= 1) s += __shfl_xor_sync(0xffffffffu, s, o);
        if (lane == 0) s_sc[p] = s;
    }
    __syncthreads();

    if (tid < Pc) {
        int p = tid;
        int j = s_j[p];
        int rb = q - 3; if (rb < 0) rb = 0;
        bool inv = (pad[b*Sc + j] != 0) || (j > q) || (j >= rb);
        float sc = inv ? -INFINITY : (s_sc[p] / 22.627416997969520780827019587355f);
        float m = sc;
#pragma unroll
        for (int o = 16; o > 0; o >>= 1) m = fmaxf(m, __shfl_xor_sync(0xffffffffu, m, o));
        float e = inv ? 0.f : expf(sc - m);
        float den = e;
#pragma unroll
        for (int o = 16; o > 0; o >>= 1) den += __shfl_xor_sync(0xffffffffu, den, o);
        s_a[p] = (den > 0.f) ? (e / den) : 0.f;
    }
    __syncthreads();

    int d = tid * 2;
    float a0 = 0.f, a1 = 0.f;
    for (int p = 0; p < Pc; p++) {
        float a = s_a[p];
        if (a != 0.f) {
            const float* vrow = g_qkvd + ((long)b*Sc + s_j[p]) * 1536 + 1024;  // dv block
            float2 vv = *reinterpret_cast<const float2*>(vrow + d);
            a0 += a * vv.x; a1 += a * vv.y;
        }
    }
    *reinterpret_cast<float2*>(g_lattn + (long)n*Ec + d) = make_float2(a0, a1);
}

// ---------------- block reduction helper -------------------------------------
__device__ __forceinline__ float block_sum_256(float v)
{
    __shared__ float sh[8];
    int lane = threadIdx.x & 31, w = threadIdx.x >> 5;
#pragma unroll
    for (int o = 16; o > 0; o >>= 1) v += __shfl_xor_sync(0xffffffffu, v, o);
    if (lane == 0) sh[w] = v;
    __syncthreads();
    float r = (lane < 8) ? sh[lane] : 0.f;
    if (w == 0) {
#pragma unroll
        for (int o = 4; o > 0; o >>= 1) r += __shfl_xor_sync(0xffffffffu, r, o);
        if (lane == 0) sh[0] = r;
    }
    __syncthreads();
    float out = sh[0];
    __syncthreads();
    return out;
}

// ---------------- gate fuse + residual + LN1 --------------------------------
__global__ __launch_bounds__(256) void fuse_ln1_kernel(
    const float* __restrict__ x, const float* __restrict__ gW, const float* __restrict__ bW)
{
    int n = blockIdx.x, tid = threadIdx.x;
    long base = (long)n*Ec + tid*2;
    float2 gg = *reinterpret_cast<const float2*>(g_gate + base);
    float2 lc = *reinterpret_cast<const float2*>(g_local + base);
    float2 lg = *reinterpret_cast<const float2*>(g_long + base);
    float2 xx = *reinterpret_cast<const float2*>(x + base);
    float v0 = xx.x + gg.x*lc.x + (1.f - gg.x)*lg.x;
    float v1 = xx.y + gg.y*lc.y + (1.f - gg.y)*lg.y;

    float mean = block_sum_256(v0 + v1) * (1.f/512.f);
    float d0 = v0 - mean, d1 = v1 - mean;
    float var = block_sum_256(d0*d0 + d1*d1) * (1.f/512.f);
    float inv = 1.f / sqrtf(var + 1e-5f);

    int c = tid*2;
    float2 go = *reinterpret_cast<const float2*>(gW + c);
    float2 bo = *reinterpret_cast<const float2*>(bW + c);
    *reinterpret_cast<float2*>(g_x1 + base) =
        make_float2(d0*inv*go.x + bo.x, d1*inv*go.y + bo.y);
}

// ---------------- residual + LN2 (final output) ------------------------------
__global__ __launch_bounds__(256) void ln2_kernel(
    const float* __restrict__ gW, const float* __restrict__ bW, float* __restrict__ out)
{
    int n = blockIdx.x, tid = threadIdx.x;
    long base = (long)n*Ec + tid*2;
    float2 xa = *reinterpret_cast<const float2*>(g_x1 + base);
    float2 fa = *reinterpret_cast<const float2*>(g_f + base);
    float v0 = xa.x + fa.x, v1 = xa.y + fa.y;

    float mean = block_sum_256(v0 + v1) * (1.f/512.f);
    float d0 = v0 - mean, d1 = v1 - mean;
    float var = block_sum_256(d0*d0 + d1*d1) * (1.f/512.f);
    float inv = 1.f / sqrtf(var + 1e-5f);

    int c = tid*2;
    float2 go = *reinterpret_cast<const float2*>(gW + c);
    float2 bo = *reinterpret_cast<const float2*>(bW + c);
    *reinterpret_cast<float2*>(out + base) =
        make_float2(d0*inv*go.x + bo.x, d1*inv*go.y + bo.y);
}

// ---------------- host launcher ----------------------------------------------
static float* sym(const void* s) { void* p = nullptr; cudaGetSymbolAddress(&p, s); return (float*)p; }

static APtrs mkap(const float* A, int K) {
    APtrs ap;
    ap.p[0] = A; ap.p[1] = A + 512; ap.p[2] = A + 1024; ap.p[3] = A + 1536;
    ap.stride = K;
    return ap;
}

extern "C" void kernel_launch(void* const* d_in, const int* in_sizes, int n_in,
                              void* d_out, int out_size)
{
    const float* x    = (const float*)d_in[0];
    const int*   pad  = (const int*)d_in[1];
    const float* in_proj_w = (const float*)d_in[2];
    const float* in_proj_b = (const float*)d_in[3];
    const float* mha_out_w = (const float*)d_in[4];
    const float* mha_out_b = (const float*)d_in[5];
    const float* dq_w = (const float*)d_in[6];
    const float* dq_b = (const float*)d_in[7];
    const float* dk_w = (const float*)d_in[8];
    const float* dk_b = (const float*)d_in[9];
    const float* dv_w = (const float*)d_in[10];
    const float* dv_b = (const float*)d_in[11];
    const float* do_w = (const float*)d_in[12];
    const float* do_b = (const float*)d_in[13];
    const float* off1_w = (const float*)d_in[14];
    const float* off1_b = (const float*)d_in[15];
    const float* off2_w = (const float*)d_in[16];
    const float* off2_b = (const float*)d_in[17];
    const float* gate1_w = (const float*)d_in[18];
    const float* gate1_b = (const float*)d_in[19];
    const float* gate2_w = (const float*)d_in[20];
    const float* gate2_b = (const float*)d_in[21];
    const float* n1_g = (const float*)d_in[22];
    const float* n1_b = (const float*)d_in[23];
    const float* n2_g = (const float*)d_in[24];
    const float* n2_b = (const float*)d_in[25];
    const float* ffn1_w = (const float*)d_in[26];
    const float* ffn1_b = (const float*)d_in[27];
    const float* ffn2_w = (const float*)d_in[28];
    const float* ffn2_b = (const float*)d_in[29];

    float* p_qkv   = sym(g_qkv);
    float* p_qkvd  = sym(g_qkvd);
    float* p_lo    = sym(g_lo);
    float* p_local = sym(g_local);
    float* p_h1    = sym(g_h1);
    float* p_offr  = sym(g_offraw);
    float* p_latt  = sym(g_lattn);
    float* p_long  = sym(g_long);
    float* p_gh    = sym(g_gh);
    float* p_gate  = sym(g_gate);
    float* p_x1    = sym(g_x1);
    float* p_ffnh  = sym(g_ffnh);
    float* p_f     = sym(g_f);

    // opt-in to >48KB dynamic smem (idempotent, cheap, capture-legal)
    cudaFuncSetAttribute(tgemm<0>, cudaFuncAttributeMaxDynamicSharedMemorySize, SMEM_BYTES);
    cudaFuncSetAttribute(tgemm<1>, cudaFuncAttributeMaxDynamicSharedMemorySize, SMEM_BYTES);
    cudaFuncSetAttribute(tgemm<2>, cudaFuncAttributeMaxDynamicSharedMemorySize, SMEM_BYTES);
    cudaFuncSetAttribute(tgemm<3>, cudaFuncAttributeMaxDynamicSharedMemorySize, SMEM_BYTES);
    cudaFuncSetAttribute(tgemm_seg, cudaFuncAttributeMaxDynamicSharedMemorySize, SMEM_BYTES);

    dim3 blk(256);

    valid_len_kernel<<<Bc, blk>>>(pad);

    // 1) fused projections off x: in_proj (12 blk) | dq|dk|dv (12 blk) | off1 (4 blk)
    {
        SegArgs sa;
        sa.nseg = 5;
        sa.s[0] = { x, in_proj_w, in_proj_b, p_qkv,  1536, 0,    0, 0  };
        sa.s[1] = { x, dq_w,      dq_b,      p_qkvd, 1536, 0,    0, 12 };
        sa.s[2] = { x, dk_w,      dk_b,      p_qkvd, 1536, 512,  0, 16 };
        sa.s[3] = { x, dv_w,      dv_b,      p_qkvd, 1536, 1024, 0, 20 };
        sa.s[4] = { x, off1_w,    off1_b,    p_h1,   512,  0,    1, 24 };
        tgemm_seg<<<dim3(28, Nt/128), blk, SMEM_BYTES>>>(sa);
    }

    // 2) local attention, offsets, sampling
    local_attn_kernel<<<(Nt*Hc)/8, blk>>>(pad);
    tgemm<2><<<dim3(256/128, Nt/128), blk, SMEM_BYTES>>>(mkap(p_h1, Ec), off2_w, off2_b, p_offr, Nt, 256, Ec);
    sample_kernel<<<(Nt*Pc)/256, blk>>>();

    // 3) long attention
    long_attn_kernel<<<Nt, blk>>>(pad);

    // 4) fused output projections: mha_out (A=g_lo) | do (A=g_lattn)
    {
        SegArgs sa;
        sa.nseg = 2;
        sa.s[0] = { p_lo,   mha_out_w, mha_out_b, p_local, 512, 0, 0, 0 };
        sa.s[1] = { p_latt, do_w,      do_b,      p_long,  512, 0, 0, 4 };
        sa.s[2] = sa.s[0]; sa.s[3] = sa.s[0]; sa.s[4] = sa.s[0];
        tgemm_seg<<<dim3(8, Nt/128), blk, SMEM_BYTES>>>(sa);
    }

    // 5) gate path: gate1 reads cat(x, local, long) via segmented A pointers
    {
        APtrs ap;
        ap.p[0] = x; ap.p[1] = p_local; ap.p[2] = p_long; ap.p[3] = x;
        ap.stride = 512;
        tgemm<1><<<dim3(Ec/128, Nt/128), blk, SMEM_BYTES>>>(ap, gate1_w, gate1_b, p_gh, Nt, Ec, 3*Ec);
    }
    tgemm<3><<<dim3(Ec/128, Nt/128), blk, SMEM_BYTES>>>(mkap(p_gh, Ec), gate2_w, gate2_b, p_gate, Nt, Ec, Ec);

    // 6) fuse + LN1
    fuse_ln1_kernel<<<Nt, blk>>>(x, n1_g, n1_b);

    // 7) FFN
    tgemm<1><<<dim3(HIDc/128, Nt/128), blk, SMEM_BYTES>>>(mkap(p_x1, Ec), ffn1_w, ffn1_b, p_ffnh, Nt, HIDc, Ec);
    tgemm<0><<<dim3(Ec/128, Nt/128), blk, SMEM_BYTES>>>(mkap(p_ffnh, HIDc), ffn2_w, ffn2_b, p_f, Nt, Ec, HIDc);

    // 8) LN2 -> output
    ln2_kernel<<<Nt, blk>>>(n2_g, n2_b, (float*)d_out);
}